// round 3
// baseline (speedup 1.0000x reference)
#include <cuda_runtime.h>

#define N_NODES 50000
#define D 256
#define E_MAX 800000

// ---------------- scratch (static device globals; no allocation) ----------------
__device__ int   g_deg[N_NODES];
__device__ int   g_rowptr[N_NODES + 1];
__device__ int   g_cursor[N_NODES];
__device__ int   g_blocksum[128];
__device__ int   g_blockoff[128];
__device__ int   g_eidx[E_MAX];
__device__ __align__(16) float g_mean[(size_t)N_NODES * D];
__device__ __align__(16) float g_h[(size_t)N_NODES * D];

// ---------------- CSR build ----------------
__global__ void zero_deg_kernel() {
    int i = blockIdx.x * blockDim.x + threadIdx.x;
    if (i < N_NODES) g_deg[i] = 0;
}

__global__ void count_kernel(const int* __restrict__ ei, int E) {
    int e = blockIdx.x * blockDim.x + threadIdx.x;
    if (e < E) {
        int dst = ei[E + e];
        atomicAdd(&g_deg[dst], 1);
    }
}

// per-block exclusive scan (512 elems/block)
__global__ void scan1_kernel() {
    __shared__ int s[512];
    int i = blockIdx.x * 512 + threadIdx.x;
    int v = (i < N_NODES) ? g_deg[i] : 0;
    s[threadIdx.x] = v;
    __syncthreads();
    for (int off = 1; off < 512; off <<= 1) {
        int t = (threadIdx.x >= off) ? s[threadIdx.x - off] : 0;
        __syncthreads();
        s[threadIdx.x] += t;
        __syncthreads();
    }
    if (i < N_NODES) g_rowptr[i] = s[threadIdx.x] - v;   // exclusive within block
    if (threadIdx.x == 511) g_blocksum[blockIdx.x] = s[511];
}

__global__ void scan2_kernel(int nblocks) {
    __shared__ int s[128];
    if (threadIdx.x < nblocks) s[threadIdx.x] = g_blocksum[threadIdx.x];
    __syncthreads();
    if (threadIdx.x == 0) {
        int off = 0;
        for (int i = 0; i < nblocks; i++) { int t = s[i]; s[i] = off; off += t; }
    }
    __syncthreads();
    if (threadIdx.x < nblocks) g_blockoff[threadIdx.x] = s[threadIdx.x];
}

__global__ void scan3_kernel(int E) {
    int i = blockIdx.x * blockDim.x + threadIdx.x;
    if (i < N_NODES) {
        int r = g_rowptr[i] + g_blockoff[i >> 9];
        g_rowptr[i] = r;
        g_cursor[i] = r;
    }
    if (i == 0) g_rowptr[N_NODES] = E;
}

__global__ void scatter_kernel(const int* __restrict__ ei, int E) {
    int e = blockIdx.x * blockDim.x + threadIdx.x;
    if (e < E) {
        int src = ei[e];
        int dst = ei[E + e];
        int pos = atomicAdd(&g_cursor[dst], 1);
        g_eidx[pos] = src;
    }
}

// ---------------- mean aggregation (atomic-free gather) ----------------
// one block per destination row; thread = feature column
// FROM_H: read from g_h (device global) instead of the param pointer.
template <bool FROM_H>
__global__ void aggregate_kernel(const float* __restrict__ in_param) {
    const float* __restrict__ in = FROM_H ? (const float*)g_h : in_param;
    int row = blockIdx.x;
    int col = threadIdx.x;
    int start = g_rowptr[row];
    int end   = g_rowptr[row + 1];
    float acc = 0.f;
    int e = start;
    for (; e + 4 <= end; e += 4) {
        int s0 = g_eidx[e + 0];
        int s1 = g_eidx[e + 1];
        int s2 = g_eidx[e + 2];
        int s3 = g_eidx[e + 3];
        float v0 = in[s0 * D + col];
        float v1 = in[s1 * D + col];
        float v2 = in[s2 * D + col];
        float v3 = in[s3 * D + col];
        acc += (v0 + v1) + (v2 + v3);
    }
    for (; e < end; e++) acc += in[g_eidx[e] * D + col];
    int deg = end - start;
    g_mean[(size_t)row * D + col] = (deg > 0) ? acc / (float)deg : 0.f;
}

// ---------------- fused GEMM: out = g_mean @ Wl + Aself @ Wr + bias (opt relu) ----
// logical A = [g_mean | Aself] (M x 512), B = [Wl ; Wr] (512 x 256)
// TO_H: write to g_h (device global) instead of the out param.
#define BM 128
#define BN 128
#define BK 16
#define PAD 4

template <bool RELU, bool SELF_FROM_H, bool TO_H>
__global__ __launch_bounds__(256, 2) void gemm_kernel(
    const float* __restrict__ Aself_param,
    const float* __restrict__ Wl,
    const float* __restrict__ Wr,
    const float* __restrict__ bias,
    float* __restrict__ out_param)
{
    __shared__ float As[BK][BM + PAD];
    __shared__ float Bs[BK][BN];

    const float* __restrict__ Aself = SELF_FROM_H ? (const float*)g_h : Aself_param;
    float* __restrict__ out = TO_H ? (float*)g_h : out_param;

    int tid     = threadIdx.x;
    int block_m = blockIdx.x;
    int block_n = blockIdx.y;
    int row0    = block_m * BM;

    int tx = tid & 15;   // N direction
    int ty = tid >> 4;   // M direction

    float acc[8][8];
#pragma unroll
    for (int i = 0; i < 8; i++)
#pragma unroll
        for (int j = 0; j < 8; j++) acc[i][j] = 0.f;

    int a_row  = tid >> 2;   // 0..63
    int a_col4 = tid & 3;    // 0..3  (float4 within 16-wide k slice)
    int b_k    = tid >> 5;   // 0..7
    int b_n4   = tid & 31;   // 0..31 (float4 within 128-wide n slice)

    for (int kt = 0; kt < 32; kt++) {
        const float* Abuf = (kt < 16) ? (const float*)g_mean : Aself;
        const float* Bbuf = (kt < 16) ? Wl : Wr;
        int kbase = (kt * BK) & 255;

        // load A tile (transposed into As[k][m])
#pragma unroll
        for (int it = 0; it < 2; it++) {
            int r  = a_row + it * 64;
            int gr = row0 + r;
            float4 v = make_float4(0.f, 0.f, 0.f, 0.f);
            if (gr < N_NODES)
                v = *(const float4*)&Abuf[(size_t)gr * D + kbase + a_col4 * 4];
            As[a_col4 * 4 + 0][r] = v.x;
            As[a_col4 * 4 + 1][r] = v.y;
            As[a_col4 * 4 + 2][r] = v.z;
            As[a_col4 * 4 + 3][r] = v.w;
        }
        // load B tile
#pragma unroll
        for (int it = 0; it < 2; it++) {
            int kk = b_k + it * 8;
            float4 v = *(const float4*)&Bbuf[(size_t)(kbase + kk) * D + block_n * BN + b_n4 * 4];
            *(float4*)&Bs[kk][b_n4 * 4] = v;
        }
        __syncthreads();

#pragma unroll
        for (int k = 0; k < BK; k++) {
            float ra[8], rb[8];
            *(float4*)&ra[0] = *(const float4*)&As[k][ty * 8 + 0];
            *(float4*)&ra[4] = *(const float4*)&As[k][ty * 8 + 4];
            *(float4*)&rb[0] = *(const float4*)&Bs[k][tx * 8 + 0];
            *(float4*)&rb[4] = *(const float4*)&Bs[k][tx * 8 + 4];
#pragma unroll
            for (int i = 0; i < 8; i++)
#pragma unroll
                for (int j = 0; j < 8; j++)
                    acc[i][j] += ra[i] * rb[j];
        }
        __syncthreads();
    }

    // epilogue: bias (+ relu) and store
#pragma unroll
    for (int i = 0; i < 8; i++) {
        int gr = row0 + ty * 8 + i;
        if (gr < N_NODES) {
#pragma unroll
            for (int j0 = 0; j0 < 8; j0 += 4) {
                int gc = block_n * BN + tx * 8 + j0;
                float4 v;
                v.x = acc[i][j0 + 0] + bias[gc + 0];
                v.y = acc[i][j0 + 1] + bias[gc + 1];
                v.z = acc[i][j0 + 2] + bias[gc + 2];
                v.w = acc[i][j0 + 3] + bias[gc + 3];
                if (RELU) {
                    v.x = fmaxf(v.x, 0.f);
                    v.y = fmaxf(v.y, 0.f);
                    v.z = fmaxf(v.z, 0.f);
                    v.w = fmaxf(v.w, 0.f);
                }
                *(float4*)&out[(size_t)gr * D + gc] = v;
            }
        }
    }
}

// ---------------- launch ----------------
extern "C" void kernel_launch(void* const* d_in, const int* in_sizes, int n_in,
                              void* d_out, int out_size)
{
    const float* x   = (const float*)d_in[0];
    const int*   ei  = (const int*)d_in[1];     // JAX randint -> int32 (x64 disabled)
    const float* W1l = (const float*)d_in[2];
    const float* b1  = (const float*)d_in[3];
    const float* W1r = (const float*)d_in[4];
    const float* W2l = (const float*)d_in[5];
    const float* b2  = (const float*)d_in[6];
    const float* W2r = (const float*)d_in[7];
    float*       out = (float*)d_out;

    int E = in_sizes[1] / 2;
    if (E > E_MAX) E = E_MAX;

    int nscan = (N_NODES + 511) / 512;   // 98

    // CSR build
    zero_deg_kernel<<<(N_NODES + 255) / 256, 256>>>();
    count_kernel<<<(E + 255) / 256, 256>>>(ei, E);
    scan1_kernel<<<nscan, 512>>>();
    scan2_kernel<<<1, 128>>>(nscan);
    scan3_kernel<<<(N_NODES + 255) / 256, 256>>>(E);
    scatter_kernel<<<(E + 255) / 256, 256>>>(ei, E);

    dim3 ggrid((N_NODES + BM - 1) / BM, D / BN);

    // layer 1: h = relu(mean(x) @ W1l + x @ W1r + b1)  -> g_h
    aggregate_kernel<false><<<N_NODES, D>>>(x);
    gemm_kernel<true, false, true><<<ggrid, 256>>>(x, W1l, W1r, b1, nullptr);

    // layer 2: out = mean(g_h) @ W2l + g_h @ W2r + b2  -> d_out
    aggregate_kernel<true><<<N_NODES, D>>>(nullptr);
    gemm_kernel<false, true, false><<<ggrid, 256>>>(nullptr, W2l, W2r, b2, out);
}

// round 4
// speedup vs baseline: 1.1697x; 1.1697x over previous
#include <cuda_runtime.h>
#include <cstdint>

#define N_NODES 50000
#define D 256
#define E_MAX 800000

// ---------------- scratch (static device globals; no allocation) ----------------
__device__ int   g_deg[N_NODES];
__device__ int   g_rowptr[N_NODES + 1];
__device__ int   g_cursor[N_NODES];
__device__ int   g_blocksum[128];
__device__ int   g_blockoff[128];
__device__ int   g_eidx[E_MAX];
__device__ __align__(16) float g_mean[(size_t)N_NODES * D];
__device__ __align__(16) float g_h[(size_t)N_NODES * D];

// ---------------- CSR build ----------------
__global__ void zero_deg_kernel() {
    int i = blockIdx.x * blockDim.x + threadIdx.x;
    if (i < N_NODES) g_deg[i] = 0;
}

__global__ void count_kernel(const int* __restrict__ ei, int E) {
    int e = blockIdx.x * blockDim.x + threadIdx.x;
    if (e < E) {
        int dst = ei[E + e];
        atomicAdd(&g_deg[dst], 1);
    }
}

__global__ void scan1_kernel() {
    __shared__ int s[512];
    int i = blockIdx.x * 512 + threadIdx.x;
    int v = (i < N_NODES) ? g_deg[i] : 0;
    s[threadIdx.x] = v;
    __syncthreads();
    for (int off = 1; off < 512; off <<= 1) {
        int t = (threadIdx.x >= off) ? s[threadIdx.x - off] : 0;
        __syncthreads();
        s[threadIdx.x] += t;
        __syncthreads();
    }
    if (i < N_NODES) g_rowptr[i] = s[threadIdx.x] - v;
    if (threadIdx.x == 511) g_blocksum[blockIdx.x] = s[511];
}

__global__ void scan2_kernel(int nblocks) {
    __shared__ int s[128];
    if (threadIdx.x < nblocks) s[threadIdx.x] = g_blocksum[threadIdx.x];
    __syncthreads();
    if (threadIdx.x == 0) {
        int off = 0;
        for (int i = 0; i < nblocks; i++) { int t = s[i]; s[i] = off; off += t; }
    }
    __syncthreads();
    if (threadIdx.x < nblocks) g_blockoff[threadIdx.x] = s[threadIdx.x];
}

__global__ void scan3_kernel(int E) {
    int i = blockIdx.x * blockDim.x + threadIdx.x;
    if (i < N_NODES) {
        int r = g_rowptr[i] + g_blockoff[i >> 9];
        g_rowptr[i] = r;
        g_cursor[i] = r;
    }
    if (i == 0) g_rowptr[N_NODES] = E;
}

__global__ void scatter_kernel(const int* __restrict__ ei, int E) {
    int e = blockIdx.x * blockDim.x + threadIdx.x;
    if (e < E) {
        int src = ei[e];
        int dst = ei[E + e];
        int pos = atomicAdd(&g_cursor[dst], 1);
        g_eidx[pos] = src;
    }
}

// ---------------- mean aggregation (atomic-free gather) ----------------
template <bool FROM_H>
__global__ void aggregate_kernel(const float* __restrict__ in_param) {
    const float* __restrict__ in = FROM_H ? (const float*)g_h : in_param;
    int row = blockIdx.x;
    int col = threadIdx.x;
    int start = g_rowptr[row];
    int end   = g_rowptr[row + 1];
    float acc = 0.f;
    int e = start;
    for (; e + 4 <= end; e += 4) {
        int s0 = g_eidx[e + 0];
        int s1 = g_eidx[e + 1];
        int s2 = g_eidx[e + 2];
        int s3 = g_eidx[e + 3];
        float v0 = in[s0 * D + col];
        float v1 = in[s1 * D + col];
        float v2 = in[s2 * D + col];
        float v3 = in[s3 * D + col];
        acc += (v0 + v1) + (v2 + v3);
    }
    for (; e < end; e++) acc += in[g_eidx[e] * D + col];
    int deg = end - start;
    g_mean[(size_t)row * D + col] = (deg > 0) ? acc / (float)deg : 0.f;
}

// ---------------- TF32 tensor-core GEMM with 3-term error compensation --------
// out = g_mean @ Wl + Aself @ Wr + bias  (opt relu)
// logical A = [g_mean | Aself] (M x 512), B = [Wl ; Wr] (512 x 256)
#define BM 128
#define BN 128
#define BK 16
#define A_STRIDE 20    // (20*m + k) % 32 distinct over fragment lanes -> conflict-free
#define B_STRIDE 136   // (136*k + n) % 32 = (8k+n)%32 distinct -> conflict-free

__device__ __forceinline__ uint32_t f2tf32(float v) {
    uint32_t r;
    asm("cvt.rna.tf32.f32 %0, %1;" : "=r"(r) : "f"(v));
    return r;
}

__device__ __forceinline__ void mma_tf32(float* c, const uint32_t* a, const uint32_t* b) {
    asm volatile(
        "mma.sync.aligned.m16n8k8.row.col.f32.tf32.tf32.f32 "
        "{%0,%1,%2,%3}, {%4,%5,%6,%7}, {%8,%9}, {%0,%1,%2,%3};\n"
        : "+f"(c[0]), "+f"(c[1]), "+f"(c[2]), "+f"(c[3])
        : "r"(a[0]), "r"(a[1]), "r"(a[2]), "r"(a[3]), "r"(b[0]), "r"(b[1]));
}

template <bool RELU, bool SELF_FROM_H, bool TO_H>
__global__ __launch_bounds__(256) void gemm_tc_kernel(
    const float* __restrict__ Aself_param,
    const float* __restrict__ Wl,
    const float* __restrict__ Wr,
    const float* __restrict__ bias,
    float* __restrict__ out_param)
{
    __shared__ float As_hi[BM][A_STRIDE];
    __shared__ float As_lo[BM][A_STRIDE];
    __shared__ float Bs_hi[BK][B_STRIDE];
    __shared__ float Bs_lo[BK][B_STRIDE];

    const float* __restrict__ Aself = SELF_FROM_H ? (const float*)g_h : Aself_param;
    float* __restrict__ out = TO_H ? (float*)g_h : out_param;

    int tid  = threadIdx.x;
    int lane = tid & 31;
    int wid  = tid >> 5;
    int g    = lane >> 2;   // groupID (row within 8)
    int tg   = lane & 3;    // thread-in-group (col within 4)

    int row0 = blockIdx.x * BM;
    int nb   = blockIdx.y * BN;

    int warp_m = (wid & 1) * 64;   // 2 warps in M
    int warp_n = (wid >> 1) * 32;  // 4 warps in N

    float acc[4][4][4];
#pragma unroll
    for (int mi = 0; mi < 4; mi++)
#pragma unroll
        for (int ni = 0; ni < 4; ni++)
#pragma unroll
            for (int r = 0; r < 4; r++) acc[mi][ni][r] = 0.f;

    // gmem->reg staging indices
    int a_r  = tid >> 2;          // 0..63 (row within first half) / +64 second
    int a_c4 = tid & 3;           // float4 within the 16-wide k slice
    int b_k  = tid >> 5;          // 0..7 / +8
    int b_n4 = tid & 31;          // float4 within 128-wide n slice

    float4 aReg[2], bReg[2];

    auto load_tile = [&](int kt) {
        const float* Abuf = (kt < 16) ? (const float*)g_mean : Aself;
        const float* Bbuf = (kt < 16) ? Wl : Wr;
        int kbase = (kt * BK) & 255;
#pragma unroll
        for (int it = 0; it < 2; it++) {
            int r  = a_r + it * 64;
            int gr = row0 + r;
            aReg[it] = make_float4(0.f, 0.f, 0.f, 0.f);
            if (gr < N_NODES)
                aReg[it] = *(const float4*)&Abuf[(size_t)gr * D + kbase + a_c4 * 4];
        }
#pragma unroll
        for (int it = 0; it < 2; it++) {
            int kk = b_k + it * 8;
            bReg[it] = *(const float4*)&Bbuf[(size_t)(kbase + kk) * D + nb + b_n4 * 4];
        }
    };

    auto store_tile = [&]() {
#pragma unroll
        for (int it = 0; it < 2; it++) {
            int r = a_r + it * 64;
            float4 v = aReg[it];
            float4 hi, lo;
            hi.x = __uint_as_float(f2tf32(v.x)); lo.x = __uint_as_float(f2tf32(v.x - hi.x));
            hi.y = __uint_as_float(f2tf32(v.y)); lo.y = __uint_as_float(f2tf32(v.y - hi.y));
            hi.z = __uint_as_float(f2tf32(v.z)); lo.z = __uint_as_float(f2tf32(v.z - hi.z));
            hi.w = __uint_as_float(f2tf32(v.w)); lo.w = __uint_as_float(f2tf32(v.w - hi.w));
            *(float4*)&As_hi[r][a_c4 * 4] = hi;
            *(float4*)&As_lo[r][a_c4 * 4] = lo;
        }
#pragma unroll
        for (int it = 0; it < 2; it++) {
            int kk = b_k + it * 8;
            float4 v = bReg[it];
            float4 hi, lo;
            hi.x = __uint_as_float(f2tf32(v.x)); lo.x = __uint_as_float(f2tf32(v.x - hi.x));
            hi.y = __uint_as_float(f2tf32(v.y)); lo.y = __uint_as_float(f2tf32(v.y - hi.y));
            hi.z = __uint_as_float(f2tf32(v.z)); lo.z = __uint_as_float(f2tf32(v.z - hi.z));
            hi.w = __uint_as_float(f2tf32(v.w)); lo.w = __uint_as_float(f2tf32(v.w - hi.w));
            *(float4*)&Bs_hi[kk][b_n4 * 4] = hi;
            *(float4*)&Bs_lo[kk][b_n4 * 4] = lo;
        }
    };

    load_tile(0);

    for (int kt = 0; kt < 32; kt++) {
        store_tile();
        __syncthreads();
        if (kt + 1 < 32) load_tile(kt + 1);   // prefetch overlaps with MMA phase

#pragma unroll
        for (int ks = 0; ks < 2; ks++) {
            int kc = ks * 8;
            uint32_t ah[4][4], al[4][4];
#pragma unroll
            for (int mi = 0; mi < 4; mi++) {
                int r = warp_m + mi * 16 + g;
                ah[mi][0] = __float_as_uint(As_hi[r][kc + tg]);
                ah[mi][1] = __float_as_uint(As_hi[r + 8][kc + tg]);
                ah[mi][2] = __float_as_uint(As_hi[r][kc + tg + 4]);
                ah[mi][3] = __float_as_uint(As_hi[r + 8][kc + tg + 4]);
                al[mi][0] = __float_as_uint(As_lo[r][kc + tg]);
                al[mi][1] = __float_as_uint(As_lo[r + 8][kc + tg]);
                al[mi][2] = __float_as_uint(As_lo[r][kc + tg + 4]);
                al[mi][3] = __float_as_uint(As_lo[r + 8][kc + tg + 4]);
            }
            uint32_t bh[4][2], bl[4][2];
#pragma unroll
            for (int ni = 0; ni < 4; ni++) {
                int c = warp_n + ni * 8 + g;
                bh[ni][0] = __float_as_uint(Bs_hi[kc + tg][c]);
                bh[ni][1] = __float_as_uint(Bs_hi[kc + tg + 4][c]);
                bl[ni][0] = __float_as_uint(Bs_lo[kc + tg][c]);
                bl[ni][1] = __float_as_uint(Bs_lo[kc + tg + 4][c]);
            }
#pragma unroll
            for (int mi = 0; mi < 4; mi++)
#pragma unroll
                for (int ni = 0; ni < 4; ni++) {
                    mma_tf32(acc[mi][ni], ah[mi], bh[ni]);
                    mma_tf32(acc[mi][ni], al[mi], bh[ni]);
                    mma_tf32(acc[mi][ni], ah[mi], bl[ni]);
                }
        }
        __syncthreads();
    }

    // epilogue: bias (+ relu), write 64x32 warp tile
#pragma unroll
    for (int mi = 0; mi < 4; mi++) {
#pragma unroll
        for (int ni = 0; ni < 4; ni++) {
            int gc = nb + warp_n + ni * 8 + tg * 2;
            float bx = bias[gc], by = bias[gc + 1];
            int gr0 = row0 + warp_m + mi * 16 + g;
            int gr1 = gr0 + 8;
            float2 v0, v1;
            v0.x = acc[mi][ni][0] + bx; v0.y = acc[mi][ni][1] + by;
            v1.x = acc[mi][ni][2] + bx; v1.y = acc[mi][ni][3] + by;
            if (RELU) {
                v0.x = fmaxf(v0.x, 0.f); v0.y = fmaxf(v0.y, 0.f);
                v1.x = fmaxf(v1.x, 0.f); v1.y = fmaxf(v1.y, 0.f);
            }
            if (gr0 < N_NODES) *(float2*)&out[(size_t)gr0 * D + gc] = v0;
            if (gr1 < N_NODES) *(float2*)&out[(size_t)gr1 * D + gc] = v1;
        }
    }
}

// ---------------- launch ----------------
extern "C" void kernel_launch(void* const* d_in, const int* in_sizes, int n_in,
                              void* d_out, int out_size)
{
    const float* x   = (const float*)d_in[0];
    const int*   ei  = (const int*)d_in[1];     // JAX randint -> int32 (x64 disabled)
    const float* W1l = (const float*)d_in[2];
    const float* b1  = (const float*)d_in[3];
    const float* W1r = (const float*)d_in[4];
    const float* W2l = (const float*)d_in[5];
    const float* b2  = (const float*)d_in[6];
    const float* W2r = (const float*)d_in[7];
    float*       out = (float*)d_out;

    int E = in_sizes[1] / 2;
    if (E > E_MAX) E = E_MAX;

    int nscan = (N_NODES + 511) / 512;

    zero_deg_kernel<<<(N_NODES + 255) / 256, 256>>>();
    count_kernel<<<(E + 255) / 256, 256>>>(ei, E);
    scan1_kernel<<<nscan, 512>>>();
    scan2_kernel<<<1, 128>>>(nscan);
    scan3_kernel<<<(N_NODES + 255) / 256, 256>>>(E);
    scatter_kernel<<<(E + 255) / 256, 256>>>(ei, E);

    dim3 ggrid((N_NODES + BM - 1) / BM, D / BN);

    // layer 1: h = relu(mean(x) @ W1l + x @ W1r + b1)  -> g_h
    aggregate_kernel<false><<<N_NODES, D>>>(x);
    gemm_tc_kernel<true, false, true><<<ggrid, 256>>>(x, W1l, W1r, b1, nullptr);

    // layer 2: out = mean(g_h) @ W2l + g_h @ W2r + b2  -> d_out
    aggregate_kernel<true><<<N_NODES, D>>>(nullptr);
    gemm_tc_kernel<false, true, false><<<ggrid, 256>>>(nullptr, W2l, W2r, b2, out);
}

// round 6
// speedup vs baseline: 1.8130x; 1.5500x over previous
#include <cuda_runtime.h>
#include <cuda_bf16.h>
#include <cstdint>

#define N_NODES 50000
#define D 256
#define E_MAX 800000

// ---------------- scratch (static device globals; no allocation) ----------------
__device__ int   g_deg[N_NODES];
__device__ int   g_rowptr[N_NODES + 1];
__device__ int   g_cursor[N_NODES];
__device__ int   g_blocksum[128];
__device__ int   g_blockoff[128];
__device__ int   g_eidx[E_MAX];
__device__ __align__(16) float    g_h[(size_t)N_NODES * D];
// A = [mean | self] as bf16 hi/lo, packed 2 bf16 per u32 along k (512 k -> 256 u32/row)
__device__ __align__(16) uint32_t g_Ahi[(size_t)N_NODES * 256];
__device__ __align__(16) uint32_t g_Alo[(size_t)N_NODES * 256];
// B^T = [Wl;Wr]^T per layer: [layer][n(256)][k2(256)] u32 (2 bf16 along k)
__device__ __align__(16) uint32_t g_Bt_hi[2 * 256 * 256];
__device__ __align__(16) uint32_t g_Bt_lo[2 * 256 * 256];

// ---------------- small helpers ----------------
__device__ __forceinline__ uint32_t smem_to_u32(const void* p) {
    uint32_t a;
    asm("{ .reg .u64 t; cvta.to.shared.u64 t, %1; cvt.u32.u64 %0, t; }" : "=r"(a) : "l"(p));
    return a;
}

__device__ __forceinline__ uint32_t pack_bf16(__nv_bfloat16 a, __nv_bfloat16 b) {
    return (uint32_t)__bfloat16_as_ushort(a) | ((uint32_t)__bfloat16_as_ushort(b) << 16);
}

// split (a,b) into bf16 hi + bf16 residual lo, packed as bf16x2 (low = a)
__device__ __forceinline__ void cvt_hilo2(float a, float b, uint32_t& hi, uint32_t& lo) {
    __nv_bfloat16 ha = __float2bfloat16(a);
    __nv_bfloat16 hb = __float2bfloat16(b);
    __nv_bfloat16 la = __float2bfloat16(a - __bfloat162float(ha));
    __nv_bfloat16 lb = __float2bfloat16(b - __bfloat162float(hb));
    hi = pack_bf16(ha, hb);
    lo = pack_bf16(la, lb);
}

#define CP_ASYNC16(dst, src, sz) \
    asm volatile("cp.async.cg.shared.global [%0], [%1], 16, %2;" \
        :: "r"(dst), "l"(src), "r"(sz) : "memory")
#define CP_COMMIT() asm volatile("cp.async.commit_group;" ::: "memory")
#define CP_WAIT1() asm volatile("cp.async.wait_group 1;" ::: "memory")
#define CP_WAIT0() asm volatile("cp.async.wait_group 0;" ::: "memory")

__device__ __forceinline__ void mma_bf16(float* c, const uint32_t* a, uint32_t b0, uint32_t b1) {
    asm volatile(
        "mma.sync.aligned.m16n8k16.row.col.f32.bf16.bf16.f32 "
        "{%0,%1,%2,%3}, {%4,%5,%6,%7}, {%8,%9}, {%0,%1,%2,%3};\n"
        : "+f"(c[0]), "+f"(c[1]), "+f"(c[2]), "+f"(c[3])
        : "r"(a[0]), "r"(a[1]), "r"(a[2]), "r"(a[3]), "r"(b0), "r"(b1));
}

// ---------------- CSR build ----------------
__global__ void zero_deg_kernel() {
    int i = blockIdx.x * blockDim.x + threadIdx.x;
    if (i < N_NODES) g_deg[i] = 0;
}

__global__ void count_kernel(const int* __restrict__ ei, int E) {
    int e = blockIdx.x * blockDim.x + threadIdx.x;
    if (e < E) atomicAdd(&g_deg[ei[E + e]], 1);
}

__global__ void scan1_kernel() {
    __shared__ int s[512];
    int i = blockIdx.x * 512 + threadIdx.x;
    int v = (i < N_NODES) ? g_deg[i] : 0;
    s[threadIdx.x] = v;
    __syncthreads();
    for (int off = 1; off < 512; off <<= 1) {
        int t = (threadIdx.x >= off) ? s[threadIdx.x - off] : 0;
        __syncthreads();
        s[threadIdx.x] += t;
        __syncthreads();
    }
    if (i < N_NODES) g_rowptr[i] = s[threadIdx.x] - v;
    if (threadIdx.x == 511) g_blocksum[blockIdx.x] = s[511];
}

__global__ void scan2_kernel(int nblocks) {
    __shared__ int s[128];
    if (threadIdx.x < nblocks) s[threadIdx.x] = g_blocksum[threadIdx.x];
    __syncthreads();
    if (threadIdx.x == 0) {
        int off = 0;
        for (int i = 0; i < nblocks; i++) { int t = s[i]; s[i] = off; off += t; }
    }
    __syncthreads();
    if (threadIdx.x < nblocks) g_blockoff[threadIdx.x] = s[threadIdx.x];
}

__global__ void scan3_kernel(int E) {
    int i = blockIdx.x * blockDim.x + threadIdx.x;
    if (i < N_NODES) {
        int r = g_rowptr[i] + g_blockoff[i >> 9];
        g_rowptr[i] = r;
        g_cursor[i] = r;
    }
    if (i == 0) g_rowptr[N_NODES] = E;
}

__global__ void scatter_kernel(const int* __restrict__ ei, int E) {
    int e = blockIdx.x * blockDim.x + threadIdx.x;
    if (e < E) {
        int src = ei[e];
        int dst = ei[E + e];
        int pos = atomicAdd(&g_cursor[dst], 1);
        g_eidx[pos] = src;
    }
}

// ---------------- W -> B^T bf16 hi/lo convert (once) ----------------
__global__ void convert_w_kernel(const float* __restrict__ W1l, const float* __restrict__ W1r,
                                 const float* __restrict__ W2l, const float* __restrict__ W2r) {
    int idx = blockIdx.x * 256 + threadIdx.x;        // 0..131071
    int layer = idx >> 16;
    int n  = (idx >> 8) & 255;
    int k2 = idx & 255;
    int k  = k2 * 2;
    const float* Wl = layer ? W2l : W1l;
    const float* Wr = layer ? W2r : W1r;
    float v0, v1;
    if (k < 256) { v0 = Wl[k * 256 + n]; v1 = Wl[(k + 1) * 256 + n]; }
    else         { v0 = Wr[(k - 256) * 256 + n]; v1 = Wr[(k - 255) * 256 + n]; }
    uint32_t hi, lo;
    cvt_hilo2(v0, v1, hi, lo);
    g_Bt_hi[idx] = hi;
    g_Bt_lo[idx] = lo;
}

// ---------------- mean aggregation + A hi/lo convert (fused) ----------------
// 128 threads/row, each handles 2 feature columns; writes bf16 hi/lo directly
template <bool FROM_H>
__global__ void aggregate_kernel(const float* __restrict__ in_param) {
    const float* __restrict__ in = FROM_H ? (const float*)g_h : in_param;
    int row = blockIdx.x;
    int t   = threadIdx.x;       // 0..127
    int c2  = t * 2;
    int start = g_rowptr[row];
    int end   = g_rowptr[row + 1];
    float a0 = 0.f, a1 = 0.f;
    int e = start;
    for (; e + 4 <= end; e += 4) {
        int s0 = g_eidx[e], s1 = g_eidx[e + 1], s2 = g_eidx[e + 2], s3 = g_eidx[e + 3];
        float2 v0 = *(const float2*)&in[(size_t)s0 * D + c2];
        float2 v1 = *(const float2*)&in[(size_t)s1 * D + c2];
        float2 v2 = *(const float2*)&in[(size_t)s2 * D + c2];
        float2 v3 = *(const float2*)&in[(size_t)s3 * D + c2];
        a0 += (v0.x + v1.x) + (v2.x + v3.x);
        a1 += (v0.y + v1.y) + (v2.y + v3.y);
    }
    for (; e < end; e++) {
        float2 v = *(const float2*)&in[(size_t)g_eidx[e] * D + c2];
        a0 += v.x; a1 += v.y;
    }
    int deg = end - start;
    float scale = (deg > 0) ? 1.f / (float)deg : 0.f;
    uint32_t hi, lo;
    cvt_hilo2(a0 * scale, a1 * scale, hi, lo);
    g_Ahi[(size_t)row * 256 + t] = hi;
    g_Alo[(size_t)row * 256 + t] = lo;
    float2 sv = *(const float2*)&in[(size_t)row * D + c2];
    cvt_hilo2(sv.x, sv.y, hi, lo);
    g_Ahi[(size_t)row * 256 + 128 + t] = hi;
    g_Alo[(size_t)row * 256 + 128 + t] = lo;
}

// ---------------- bf16 mma.sync GEMM with hi/lo compensation ----------------
// out[M x 256] = A(bf16 hi+lo, [M x 512]) @ B^T(bf16 hi+lo) + bias (opt relu)
// BM=128, BN=128 (grid.y=2), BK=32, 2-stage cp.async, stride-80B smem rows.
#define ROWB 80                        // bytes per smem row (32 bf16 data + pad)
#define TILE_BYTES (128 * ROWB)        // 10240 per matrix
#define STAGE_BYTES (4 * TILE_BYTES)   // Ahi, Alo, Bhi, Blo
#define SM_DYN (2 * STAGE_BYTES)       // 81920

template <bool RELU, bool TO_H>
__global__ __launch_bounds__(256) void gemm_bf16_kernel(
    int layer, const float* __restrict__ bias, float* __restrict__ out_param)
{
    extern __shared__ char dsm[];
    __shared__ float bias_s[128];

    float* __restrict__ out = TO_H ? (float*)g_h : out_param;
    const uint32_t* __restrict__ BtH = g_Bt_hi + (size_t)layer * 65536;
    const uint32_t* __restrict__ BtL = g_Bt_lo + (size_t)layer * 65536;

    int tid  = threadIdx.x;
    int wid  = tid >> 5;
    int lid  = tid & 31;
    int g    = lid >> 2;
    int tg   = lid & 3;
    int row0 = blockIdx.x * 128;
    int n0   = blockIdx.y * 128;

    int warp_m = (wid & 1) * 64;
    int warp_n = (wid >> 1) * 32;

    if (tid < 128) bias_s[tid] = bias[n0 + tid];

    uint32_t s_base = smem_to_u32(dsm);

    float acc[4][4][4];
#pragma unroll
    for (int mi = 0; mi < 4; mi++)
#pragma unroll
        for (int ni = 0; ni < 4; ni++)
#pragma unroll
            for (int r = 0; r < 4; r++) acc[mi][ni][r] = 0.f;

    // per-thread load role: row = tid>>1 (0..127), seg = (tid&1)*32 bytes
    int lrow = tid >> 1;
    int lseg = (tid & 1) * 32;
    int gr   = row0 + lrow;
    int a_sz = (gr < N_NODES) ? 16 : 0;
    int gra  = (gr < N_NODES) ? gr : (N_NODES - 1);
    const char* aHs = (const char*)(g_Ahi + (size_t)gra * 256) + lseg;
    const char* aLs = (const char*)(g_Alo + (size_t)gra * 256) + lseg;
    const char* bHs = (const char*)(BtH + (size_t)(n0 + lrow) * 256) + lseg;
    const char* bLs = (const char*)(BtL + (size_t)(n0 + lrow) * 256) + lseg;
    uint32_t dst_row = lrow * ROWB + lseg;

    auto tile_load = [&](int kt, int stage) {
        uint32_t st = s_base + stage * STAGE_BYTES;
        const char* srcA_hi = aHs + kt * 64;
        const char* srcA_lo = aLs + kt * 64;
        const char* srcB_hi = bHs + kt * 64;
        const char* srcB_lo = bLs + kt * 64;
        uint32_t d0 = st + dst_row;
        CP_ASYNC16(d0,                  srcA_hi,      a_sz);
        CP_ASYNC16(d0 + 16,             srcA_hi + 16, a_sz);
        CP_ASYNC16(d0 + TILE_BYTES,     srcA_lo,      a_sz);
        CP_ASYNC16(d0 + TILE_BYTES + 16,srcA_lo + 16, a_sz);
        CP_ASYNC16(d0 + 2 * TILE_BYTES,     srcB_hi,      16);
        CP_ASYNC16(d0 + 2 * TILE_BYTES + 16,srcB_hi + 16, 16);
        CP_ASYNC16(d0 + 3 * TILE_BYTES,     srcB_lo,      16);
        CP_ASYNC16(d0 + 3 * TILE_BYTES + 16,srcB_lo + 16, 16);
    };

    tile_load(0, 0);
    CP_COMMIT();

    for (int kt = 0; kt < 16; kt++) {
        int st = kt & 1;
        if (kt + 1 < 16) { tile_load(kt + 1, st ^ 1); CP_COMMIT(); CP_WAIT1(); }
        else             { CP_WAIT0(); }
        __syncthreads();

        const char* sa_h = dsm + st * STAGE_BYTES;
        const char* sa_l = sa_h + TILE_BYTES;
        const char* sb_h = sa_h + 2 * TILE_BYTES;
        const char* sb_l = sa_h + 3 * TILE_BYTES;

#pragma unroll
        for (int ks = 0; ks < 2; ks++) {
            int koff = ks * 32 + tg * 4;      // byte offset along k within row
            uint32_t bh[4][2], bl[4][2];
#pragma unroll
            for (int ni = 0; ni < 4; ni++) {
                int nrow = warp_n + ni * 8 + g;
                bh[ni][0] = *(const uint32_t*)(sb_h + nrow * ROWB + koff);
                bh[ni][1] = *(const uint32_t*)(sb_h + nrow * ROWB + koff + 16);
                bl[ni][0] = *(const uint32_t*)(sb_l + nrow * ROWB + koff);
                bl[ni][1] = *(const uint32_t*)(sb_l + nrow * ROWB + koff + 16);
            }
#pragma unroll
            for (int mi = 0; mi < 4; mi++) {
                int arow = warp_m + mi * 16 + g;
                uint32_t ah[4], al[4];
                ah[0] = *(const uint32_t*)(sa_h + arow * ROWB + koff);
                ah[1] = *(const uint32_t*)(sa_h + (arow + 8) * ROWB + koff);
                ah[2] = *(const uint32_t*)(sa_h + arow * ROWB + koff + 16);
                ah[3] = *(const uint32_t*)(sa_h + (arow + 8) * ROWB + koff + 16);
                al[0] = *(const uint32_t*)(sa_l + arow * ROWB + koff);
                al[1] = *(const uint32_t*)(sa_l + (arow + 8) * ROWB + koff);
                al[2] = *(const uint32_t*)(sa_l + arow * ROWB + koff + 16);
                al[3] = *(const uint32_t*)(sa_l + (arow + 8) * ROWB + koff + 16);
#pragma unroll
                for (int ni = 0; ni < 4; ni++) mma_bf16(acc[mi][ni], ah, bh[ni][0], bh[ni][1]);
#pragma unroll
                for (int ni = 0; ni < 4; ni++) mma_bf16(acc[mi][ni], al, bh[ni][0], bh[ni][1]);
#pragma unroll
                for (int ni = 0; ni < 4; ni++) mma_bf16(acc[mi][ni], ah, bl[ni][0], bl[ni][1]);
            }
        }
        __syncthreads();
    }

    // epilogue
#pragma unroll
    for (int mi = 0; mi < 4; mi++) {
#pragma unroll
        for (int ni = 0; ni < 4; ni++) {
            int lc = warp_n + ni * 8 + tg * 2;
            float bx = bias_s[lc], by = bias_s[lc + 1];
            int gc  = n0 + lc;
            int gr0 = row0 + warp_m + mi * 16 + g;
            int gr1 = gr0 + 8;
            float2 v0, v1;
            v0.x = acc[mi][ni][0] + bx; v0.y = acc[mi][ni][1] + by;
            v1.x = acc[mi][ni][2] + bx; v1.y = acc[mi][ni][3] + by;
            if (RELU) {
                v0.x = fmaxf(v0.x, 0.f); v0.y = fmaxf(v0.y, 0.f);
                v1.x = fmaxf(v1.x, 0.f); v1.y = fmaxf(v1.y, 0.f);
            }
            if (gr0 < N_NODES) *(float2*)&out[(size_t)gr0 * D + gc] = v0;
            if (gr1 < N_NODES) *(float2*)&out[(size_t)gr1 * D + gc] = v1;
        }
    }
}

// ---------------- launch ----------------
extern "C" void kernel_launch(void* const* d_in, const int* in_sizes, int n_in,
                              void* d_out, int out_size)
{
    const float* x   = (const float*)d_in[0];
    const int*   ei  = (const int*)d_in[1];     // JAX randint -> int32 (x64 disabled)
    const float* W1l = (const float*)d_in[2];
    const float* b1  = (const float*)d_in[3];
    const float* W1r = (const float*)d_in[4];
    const float* W2l = (const float*)d_in[5];
    const float* b2  = (const float*)d_in[6];
    const float* W2r = (const float*)d_in[7];
    float*       out = (float*)d_out;

    int E = in_sizes[1] / 2;
    if (E > E_MAX) E = E_MAX;

    int nscan = (N_NODES + 511) / 512;

    cudaFuncSetAttribute(gemm_bf16_kernel<true, true>,
                         cudaFuncAttributeMaxDynamicSharedMemorySize, SM_DYN);
    cudaFuncSetAttribute(gemm_bf16_kernel<false, false>,
                         cudaFuncAttributeMaxDynamicSharedMemorySize, SM_DYN);

    // CSR build + weight conversion
    zero_deg_kernel<<<(N_NODES + 255) / 256, 256>>>();
    count_kernel<<<(E + 255) / 256, 256>>>(ei, E);
    scan1_kernel<<<nscan, 512>>>();
    scan2_kernel<<<1, 128>>>(nscan);
    scan3_kernel<<<(N_NODES + 255) / 256, 256>>>(E);
    scatter_kernel<<<(E + 255) / 256, 256>>>(ei, E);
    convert_w_kernel<<<512, 256>>>(W1l, W1r, W2l, W2r);

    dim3 ggrid((N_NODES + 127) / 128, 2);

    // layer 1: h = relu(mean(x) @ W1l + x @ W1r + b1)  -> g_h
    aggregate_kernel<false><<<N_NODES, 128>>>(x);
    gemm_bf16_kernel<true, true><<<ggrid, 256, SM_DYN>>>(0, b1, nullptr);

    // layer 2: out = mean(g_h) @ W2l + g_h @ W2r + b2  -> d_out
    aggregate_kernel<true><<<N_NODES, 128>>>(nullptr);
    gemm_bf16_kernel<false, false><<<ggrid, 256, SM_DYN>>>(1, b2, out);
}

// round 7
// speedup vs baseline: 1.8352x; 1.0123x over previous
#include <cuda_runtime.h>
#include <cuda_bf16.h>
#include <cstdint>

#define N_NODES 50000
#define D 256
#define E_MAX 800000

// ---------------- scratch (static device globals; no allocation) ----------------
__device__ int   g_deg[N_NODES];
__device__ int   g_rowptr[N_NODES + 1];
__device__ int   g_cursor[N_NODES];
__device__ int   g_blocksum[128];
__device__ int   g_blockoff[128];
__device__ int   g_eidx[E_MAX];
__device__ __align__(16) float    g_h[(size_t)N_NODES * D];
// A = [mean | self] as bf16 hi/lo, packed 2 bf16 per u32 along k (512 k -> 256 u32/row)
__device__ __align__(16) uint32_t g_Ahi[(size_t)N_NODES * 256];
__device__ __align__(16) uint32_t g_Alo[(size_t)N_NODES * 256];
// B^T = [Wl;Wr]^T per layer: [layer][n(256)][k2(256)] u32 (2 bf16 along k)
__device__ __align__(16) uint32_t g_Bt_hi[2 * 256 * 256];
__device__ __align__(16) uint32_t g_Bt_lo[2 * 256 * 256];

// ---------------- small helpers ----------------
__device__ __forceinline__ uint32_t smem_to_u32(const void* p) {
    uint32_t a;
    asm("{ .reg .u64 t; cvta.to.shared.u64 t, %1; cvt.u32.u64 %0, t; }" : "=r"(a) : "l"(p));
    return a;
}

__device__ __forceinline__ uint32_t pack_bf16(__nv_bfloat16 a, __nv_bfloat16 b) {
    return (uint32_t)__bfloat16_as_ushort(a) | ((uint32_t)__bfloat16_as_ushort(b) << 16);
}

__device__ __forceinline__ void cvt_hilo2(float a, float b, uint32_t& hi, uint32_t& lo) {
    __nv_bfloat16 ha = __float2bfloat16(a);
    __nv_bfloat16 hb = __float2bfloat16(b);
    __nv_bfloat16 la = __float2bfloat16(a - __bfloat162float(ha));
    __nv_bfloat16 lb = __float2bfloat16(b - __bfloat162float(hb));
    hi = pack_bf16(ha, hb);
    lo = pack_bf16(la, lb);
}

#define CP_ASYNC16(dst, src, sz) \
    asm volatile("cp.async.cg.shared.global [%0], [%1], 16, %2;" \
        :: "r"(dst), "l"(src), "r"(sz) : "memory")
#define CP_COMMIT() asm volatile("cp.async.commit_group;" ::: "memory")
#define CP_WAIT1() asm volatile("cp.async.wait_group 1;" ::: "memory")
#define CP_WAIT0() asm volatile("cp.async.wait_group 0;" ::: "memory")

#define LDSM_X4(r0, r1, r2, r3, addr) \
    asm volatile("ldmatrix.sync.aligned.m8n8.x4.shared.b16 {%0,%1,%2,%3}, [%4];" \
        : "=r"(r0), "=r"(r1), "=r"(r2), "=r"(r3) : "r"(addr))
#define LDSM_X2(r0, r1, addr) \
    asm volatile("ldmatrix.sync.aligned.m8n8.x2.shared.b16 {%0,%1}, [%2];" \
        : "=r"(r0), "=r"(r1) : "r"(addr))

__device__ __forceinline__ void mma_bf16(float* c, const uint32_t* a, uint32_t b0, uint32_t b1) {
    asm volatile(
        "mma.sync.aligned.m16n8k16.row.col.f32.bf16.bf16.f32 "
        "{%0,%1,%2,%3}, {%4,%5,%6,%7}, {%8,%9}, {%0,%1,%2,%3};\n"
        : "+f"(c[0]), "+f"(c[1]), "+f"(c[2]), "+f"(c[3])
        : "r"(a[0]), "r"(a[1]), "r"(a[2]), "r"(a[3]), "r"(b0), "r"(b1));
}

// ---------------- CSR build ----------------
__global__ void zero_deg_kernel() {
    int i = blockIdx.x * blockDim.x + threadIdx.x;
    if (i < N_NODES) g_deg[i] = 0;
}

__global__ void count_kernel(const int* __restrict__ ei, int E) {
    int e = blockIdx.x * blockDim.x + threadIdx.x;
    if (e < E) atomicAdd(&g_deg[ei[E + e]], 1);
}

__global__ void scan1_kernel() {
    __shared__ int s[512];
    int i = blockIdx.x * 512 + threadIdx.x;
    int v = (i < N_NODES) ? g_deg[i] : 0;
    s[threadIdx.x] = v;
    __syncthreads();
    for (int off = 1; off < 512; off <<= 1) {
        int t = (threadIdx.x >= off) ? s[threadIdx.x - off] : 0;
        __syncthreads();
        s[threadIdx.x] += t;
        __syncthreads();
    }
    if (i < N_NODES) g_rowptr[i] = s[threadIdx.x] - v;
    if (threadIdx.x == 511) g_blocksum[blockIdx.x] = s[511];
}

__global__ void scan2_kernel(int nblocks) {
    __shared__ int s[128];
    if (threadIdx.x < nblocks) s[threadIdx.x] = g_blocksum[threadIdx.x];
    __syncthreads();
    if (threadIdx.x == 0) {
        int off = 0;
        for (int i = 0; i < nblocks; i++) { int t = s[i]; s[i] = off; off += t; }
    }
    __syncthreads();
    if (threadIdx.x < nblocks) g_blockoff[threadIdx.x] = s[threadIdx.x];
}

__global__ void scan3_kernel(int E) {
    int i = blockIdx.x * blockDim.x + threadIdx.x;
    if (i < N_NODES) {
        int r = g_rowptr[i] + g_blockoff[i >> 9];
        g_rowptr[i] = r;
        g_cursor[i] = r;
    }
    if (i == 0) g_rowptr[N_NODES] = E;
}

__global__ void scatter_kernel(const int* __restrict__ ei, int E) {
    int e = blockIdx.x * blockDim.x + threadIdx.x;
    if (e < E) {
        int src = ei[e];
        int dst = ei[E + e];
        int pos = atomicAdd(&g_cursor[dst], 1);
        g_eidx[pos] = src;
    }
}

// ---------------- W -> B^T bf16 hi/lo convert (once) ----------------
__global__ void convert_w_kernel(const float* __restrict__ W1l, const float* __restrict__ W1r,
                                 const float* __restrict__ W2l, const float* __restrict__ W2r) {
    int idx = blockIdx.x * 256 + threadIdx.x;        // 0..131071
    int layer = idx >> 16;
    int n  = (idx >> 8) & 255;
    int k2 = idx & 255;
    int k  = k2 * 2;
    const float* Wl = layer ? W2l : W1l;
    const float* Wr = layer ? W2r : W1r;
    float v0, v1;
    if (k < 256) { v0 = Wl[k * 256 + n]; v1 = Wl[(k + 1) * 256 + n]; }
    else         { v0 = Wr[(k - 256) * 256 + n]; v1 = Wr[(k - 255) * 256 + n]; }
    uint32_t hi, lo;
    cvt_hilo2(v0, v1, hi, lo);
    g_Bt_hi[idx] = hi;
    g_Bt_lo[idx] = lo;
}

// ---------------- mean aggregation + A hi/lo convert (fused) ----------------
template <bool FROM_H>
__global__ void aggregate_kernel(const float* __restrict__ in_param) {
    const float* __restrict__ in = FROM_H ? (const float*)g_h : in_param;
    int row = blockIdx.x;
    int t   = threadIdx.x;       // 0..127
    int c2  = t * 2;
    int start = g_rowptr[row];
    int end   = g_rowptr[row + 1];
    float a0 = 0.f, a1 = 0.f;
    int e = start;
    for (; e + 4 <= end; e += 4) {
        int s0 = g_eidx[e], s1 = g_eidx[e + 1], s2 = g_eidx[e + 2], s3 = g_eidx[e + 3];
        float2 v0 = *(const float2*)&in[(size_t)s0 * D + c2];
        float2 v1 = *(const float2*)&in[(size_t)s1 * D + c2];
        float2 v2 = *(const float2*)&in[(size_t)s2 * D + c2];
        float2 v3 = *(const float2*)&in[(size_t)s3 * D + c2];
        a0 += (v0.x + v1.x) + (v2.x + v3.x);
        a1 += (v0.y + v1.y) + (v2.y + v3.y);
    }
    for (; e < end; e++) {
        float2 v = *(const float2*)&in[(size_t)g_eidx[e] * D + c2];
        a0 += v.x; a1 += v.y;
    }
    int deg = end - start;
    float scale = (deg > 0) ? 1.f / (float)deg : 0.f;
    uint32_t hi, lo;
    cvt_hilo2(a0 * scale, a1 * scale, hi, lo);
    g_Ahi[(size_t)row * 256 + t] = hi;
    g_Alo[(size_t)row * 256 + t] = lo;
    float2 sv = *(const float2*)&in[(size_t)row * D + c2];
    cvt_hilo2(sv.x, sv.y, hi, lo);
    g_Ahi[(size_t)row * 256 + 128 + t] = hi;
    g_Alo[(size_t)row * 256 + 128 + t] = lo;
}

// ---------------- bf16 mma.sync GEMM, ldmatrix fragment loads ----------------
// out[M x 256] = A(bf16 hi+lo, [M x 512]) @ B^T(bf16 hi+lo) + bias (opt relu)
// BM=128, BN=128 (grid.y=2), BK=32, 2-stage cp.async, stride-80B smem rows.
#define ROWB 80
#define TILE_BYTES (128 * ROWB)        // 10240 per matrix
#define STAGE_BYTES (4 * TILE_BYTES)   // Ahi, Alo, Bhi, Blo
#define SM_DYN (2 * STAGE_BYTES)       // 81920

template <bool RELU, bool TO_H>
__global__ __launch_bounds__(256, 2) void gemm_bf16_kernel(
    int layer, const float* __restrict__ bias, float* __restrict__ out_param)
{
    extern __shared__ char dsm[];
    __shared__ float bias_s[128];

    float* __restrict__ out = TO_H ? (float*)g_h : out_param;
    const uint32_t* __restrict__ BtH = g_Bt_hi + (size_t)layer * 65536;
    const uint32_t* __restrict__ BtL = g_Bt_lo + (size_t)layer * 65536;

    int tid  = threadIdx.x;
    int wid  = tid >> 5;
    int lid  = tid & 31;
    int g    = lid >> 2;
    int tg   = lid & 3;
    int row0 = blockIdx.x * 128;
    int n0   = blockIdx.y * 128;

    int warp_m = (wid & 1) * 64;
    int warp_n = (wid >> 1) * 32;

    if (tid < 128) bias_s[tid] = bias[n0 + tid];

    uint32_t s_base = smem_to_u32(dsm);

    // per-lane ldmatrix offsets (bytes)
    // A x4: matrix idx q = lid>>3: rows += (q&1)*8, kbytes += (q>>1)*16
    uint32_t a_lane_off = (uint32_t)(((lid & 7) + ((lid >> 3) & 1) * 8) * ROWB + (lid >> 4) * 16);
    // B x2: q = (lid&15)>>3: kbytes += q*16 ; row = lid&7
    uint32_t b_lane_off = (uint32_t)((lid & 7) * ROWB + (((lid & 15) >> 3)) * 16);

    float acc[4][4][4];
#pragma unroll
    for (int mi = 0; mi < 4; mi++)
#pragma unroll
        for (int ni = 0; ni < 4; ni++)
#pragma unroll
            for (int r = 0; r < 4; r++) acc[mi][ni][r] = 0.f;

    // per-thread cp.async role: row = tid>>1 (0..127), seg = (tid&1)*32 bytes
    int lrow = tid >> 1;
    int lseg = (tid & 1) * 32;
    int gr   = row0 + lrow;
    int a_sz = (gr < N_NODES) ? 16 : 0;
    int gra  = (gr < N_NODES) ? gr : (N_NODES - 1);
    const char* aHs = (const char*)(g_Ahi + (size_t)gra * 256) + lseg;
    const char* aLs = (const char*)(g_Alo + (size_t)gra * 256) + lseg;
    const char* bHs = (const char*)(BtH + (size_t)(n0 + lrow) * 256) + lseg;
    const char* bLs = (const char*)(BtL + (size_t)(n0 + lrow) * 256) + lseg;
    uint32_t dst_row = lrow * ROWB + lseg;

    auto tile_load = [&](int kt, int stage) {
        uint32_t st = s_base + stage * STAGE_BYTES;
        const char* srcA_hi = aHs + kt * 64;
        const char* srcA_lo = aLs + kt * 64;
        const char* srcB_hi = bHs + kt * 64;
        const char* srcB_lo = bLs + kt * 64;
        uint32_t d0 = st + dst_row;
        CP_ASYNC16(d0,                  srcA_hi,      a_sz);
        CP_ASYNC16(d0 + 16,             srcA_hi + 16, a_sz);
        CP_ASYNC16(d0 + TILE_BYTES,     srcA_lo,      a_sz);
        CP_ASYNC16(d0 + TILE_BYTES + 16,srcA_lo + 16, a_sz);
        CP_ASYNC16(d0 + 2 * TILE_BYTES,     srcB_hi,      16);
        CP_ASYNC16(d0 + 2 * TILE_BYTES + 16,srcB_hi + 16, 16);
        CP_ASYNC16(d0 + 3 * TILE_BYTES,     srcB_lo,      16);
        CP_ASYNC16(d0 + 3 * TILE_BYTES + 16,srcB_lo + 16, 16);
    };

    tile_load(0, 0);
    CP_COMMIT();

    for (int kt = 0; kt < 16; kt++) {
        int st = kt & 1;
        if (kt + 1 < 16) { tile_load(kt + 1, st ^ 1); CP_COMMIT(); CP_WAIT1(); }
        else             { CP_WAIT0(); }
        __syncthreads();

        uint32_t sa_h = s_base + st * STAGE_BYTES;
        uint32_t sa_l = sa_h + TILE_BYTES;
        uint32_t sb_h = sa_h + 2 * TILE_BYTES;
        uint32_t sb_l = sa_h + 3 * TILE_BYTES;

#pragma unroll
        for (int ks = 0; ks < 2; ks++) {
            uint32_t koff = ks * 32;
            uint32_t bh[4][2], bl[4][2];
#pragma unroll
            for (int ni = 0; ni < 4; ni++) {
                uint32_t nbase = (uint32_t)((warp_n + ni * 8) * ROWB) + koff;
                LDSM_X2(bh[ni][0], bh[ni][1], sb_h + nbase + b_lane_off);
                LDSM_X2(bl[ni][0], bl[ni][1], sb_l + nbase + b_lane_off);
            }
#pragma unroll
            for (int mi = 0; mi < 4; mi++) {
                uint32_t mbase = (uint32_t)((warp_m + mi * 16) * ROWB) + koff;
                uint32_t ah[4], al[4];
                LDSM_X4(ah[0], ah[1], ah[2], ah[3], sa_h + mbase + a_lane_off);
                LDSM_X4(al[0], al[1], al[2], al[3], sa_l + mbase + a_lane_off);
#pragma unroll
                for (int ni = 0; ni < 4; ni++) mma_bf16(acc[mi][ni], ah, bh[ni][0], bh[ni][1]);
#pragma unroll
                for (int ni = 0; ni < 4; ni++) mma_bf16(acc[mi][ni], al, bh[ni][0], bh[ni][1]);
#pragma unroll
                for (int ni = 0; ni < 4; ni++) mma_bf16(acc[mi][ni], ah, bl[ni][0], bl[ni][1]);
            }
        }
        __syncthreads();
    }

    // epilogue
#pragma unroll
    for (int mi = 0; mi < 4; mi++) {
#pragma unroll
        for (int ni = 0; ni < 4; ni++) {
            int lc = warp_n + ni * 8 + tg * 2;
            float bx = bias_s[lc], by = bias_s[lc + 1];
            int gc  = n0 + lc;
            int gr0 = row0 + warp_m + mi * 16 + g;
            int gr1 = gr0 + 8;
            float2 v0, v1;
            v0.x = acc[mi][ni][0] + bx; v0.y = acc[mi][ni][1] + by;
            v1.x = acc[mi][ni][2] + bx; v1.y = acc[mi][ni][3] + by;
            if (RELU) {
                v0.x = fmaxf(v0.x, 0.f); v0.y = fmaxf(v0.y, 0.f);
                v1.x = fmaxf(v1.x, 0.f); v1.y = fmaxf(v1.y, 0.f);
            }
            if (gr0 < N_NODES) *(float2*)&out[(size_t)gr0 * D + gc] = v0;
            if (gr1 < N_NODES) *(float2*)&out[(size_t)gr1 * D + gc] = v1;
        }
    }
}

// ---------------- launch ----------------
extern "C" void kernel_launch(void* const* d_in, const int* in_sizes, int n_in,
                              void* d_out, int out_size)
{
    const float* x   = (const float*)d_in[0];
    const int*   ei  = (const int*)d_in[1];     // JAX randint -> int32 (x64 disabled)
    const float* W1l = (const float*)d_in[2];
    const float* b1  = (const float*)d_in[3];
    const float* W1r = (const float*)d_in[4];
    const float* W2l = (const float*)d_in[5];
    const float* b2  = (const float*)d_in[6];
    const float* W2r = (const float*)d_in[7];
    float*       out = (float*)d_out;

    int E = in_sizes[1] / 2;
    if (E > E_MAX) E = E_MAX;

    int nscan = (N_NODES + 511) / 512;

    cudaFuncSetAttribute(gemm_bf16_kernel<true, true>,
                         cudaFuncAttributeMaxDynamicSharedMemorySize, SM_DYN);
    cudaFuncSetAttribute(gemm_bf16_kernel<false, false>,
                         cudaFuncAttributeMaxDynamicSharedMemorySize, SM_DYN);

    // CSR build + weight conversion
    zero_deg_kernel<<<(N_NODES + 255) / 256, 256>>>();
    count_kernel<<<(E + 255) / 256, 256>>>(ei, E);
    scan1_kernel<<<nscan, 512>>>();
    scan2_kernel<<<1, 128>>>(nscan);
    scan3_kernel<<<(N_NODES + 255) / 256, 256>>>(E);
    scatter_kernel<<<(E + 255) / 256, 256>>>(ei, E);
    convert_w_kernel<<<512, 256>>>(W1l, W1r, W2l, W2r);

    dim3 ggrid((N_NODES + 127) / 128, 2);

    // layer 1: h = relu(mean(x) @ W1l + x @ W1r + b1)  -> g_h
    aggregate_kernel<false><<<N_NODES, 128>>>(x);
    gemm_bf16_kernel<true, true><<<ggrid, 256, SM_DYN>>>(0, b1, nullptr);

    // layer 2: out = mean(g_h) @ W2l + g_h @ W2r + b2  -> d_out
    aggregate_kernel<true><<<N_NODES, 128>>>(nullptr);
    gemm_bf16_kernel<false, false><<<ggrid, 256, SM_DYN>>>(1, b2, out);
}